// round 14
// baseline (speedup 1.0000x reference)
#include <cuda_runtime.h>
#include <cuda_fp16.h>
#include <cstdint>
#include <cstddef>

#define BATCH 2
#define DIM   256
#define NPIX  4096
#define OCH   768
#define KCH   64          // K halves per chunk
#define PITCH_H 72        // padded pitch (halves) for k_qkv/k_out tiles
#define NTHREADS 256      // 8 warps, 2x4 grid of 64x32 warp tiles -> CTA 128x128
#define NSPLIT 2
#define TILE_HALVES (128 * PITCH_H)
#define STAGE_HALVES (2 * TILE_HALVES)
#define SMEM_BYTES (3 * STAGE_HALVES * 2)     // 110592 B (k_qkv / k_out)
#define TILE_SW 16384                          // 128 rows x 128 B swizzled tile
#define SMEM_E_BYTES (7 * TILE_SW)             // 4 A-chunks + 3 B-stages = 114688 B

static constexpr float M0 = 1.0f / 4096.0f + 1e-8f;  // exp(logm)

// ---------------- scratch ----------------
__device__ __align__(16) __half g_xTh[BATCH * NPIX * DIM];
__device__ __align__(16) __half g_Wh [OCH * DIM];
__device__ __align__(16) __half g_qh [BATCH * NPIX * DIM];
__device__ __align__(16) __half g_kh [BATCH * NPIX * DIM];
__device__ __align__(16) float  g_vT [BATCH * DIM * NPIX];
__device__ __align__(16) __half g_vvTh[BATCH * DIM * NPIX];
__device__ __align__(16) __half g_Eh [(size_t)BATCH * NPIX * NPIX];
__device__ __align__(16) float g_op [NSPLIT][BATCH * DIM * NPIX];
__device__ __align__(16) float g_r [BATCH * NPIX];
__device__ __align__(16) float g_s [BATCH * NPIX];
__device__ __align__(16) float g_eu[BATCH * NPIX];
__device__ __align__(16) float g_ev[BATCH * NPIX];

// ---------------- helpers ----------------
__device__ __forceinline__ uint32_t smem_u32(const void* p) {
    uint32_t a;
    asm("{ .reg .u64 t; cvta.to.shared.u64 t, %1; cvt.u32.u64 %0, t; }" : "=r"(a) : "l"(p));
    return a;
}
__device__ __forceinline__ void cp16(void* s, const void* g) {
    asm volatile("cp.async.cg.shared.global [%0], [%1], 16;" :: "r"(smem_u32(s)), "l"(g));
}
__device__ __forceinline__ void cp16a(uint32_t saddr, const void* g) {
    asm volatile("cp.async.cg.shared.global [%0], [%1], 16;" :: "r"(saddr), "l"(g));
}
#define CP_COMMIT() asm volatile("cp.async.commit_group;" ::: "memory")
#define CP_WAIT1()  asm volatile("cp.async.wait_group 1;" ::: "memory")

__device__ __forceinline__ void ldsm4(uint32_t& r0, uint32_t& r1, uint32_t& r2, uint32_t& r3,
                                      uint32_t addr) {
    asm volatile("ldmatrix.sync.aligned.m8n8.x4.shared.b16 {%0,%1,%2,%3}, [%4];"
                 : "=r"(r0), "=r"(r1), "=r"(r2), "=r"(r3) : "r"(addr));
}
__device__ __forceinline__ void mma_f16(float (&d)[4], const uint32_t (&a)[4], const uint32_t (&b)[2]) {
    asm volatile(
        "mma.sync.aligned.m16n8k16.row.col.f32.f16.f16.f32 "
        "{%0,%1,%2,%3}, {%4,%5,%6,%7}, {%8,%9}, {%0,%1,%2,%3};"
        : "+f"(d[0]), "+f"(d[1]), "+f"(d[2]), "+f"(d[3])
        : "r"(a[0]), "r"(a[1]), "r"(a[2]), "r"(a[3]), "r"(b[0]), "r"(b[1]));
}

// padded loader (k_qkv / k_out): 128 rows x 64 halves
__device__ __forceinline__ void load_rm(__half* sbuf, const __half* src, size_t ld, int tid) {
#pragma unroll
    for (int i = 0; i < 4; i++) {
        int idx = tid + i * NTHREADS;
        int r = idx >> 3;
        int c = (idx & 7) << 3;
        cp16(&sbuf[r * PITCH_H + c], src + (size_t)r * ld + c);
    }
}
// swizzled loader (k_gemmE): 128 rows x 64 halves, row = 128 B, chunk^(r&7)
__device__ __forceinline__ void load_sw(uint32_t sdst, const __half* src, size_t ld, int tid) {
#pragma unroll
    for (int i = 0; i < 4; i++) {
        int idx = tid + i * NTHREADS;
        int r = idx >> 3;
        int c = idx & 7;
        cp16a(sdst + (uint32_t)(r * 128 + ((c ^ (r & 7)) << 4)),
              src + (size_t)r * ld + c * 8);
    }
}

// ---------------- padded 128x128 GEMM mainloop (k_qkv / k_out) ----------------
__device__ __forceinline__ void gemm_main(float (&acc)[4][4][4],
                                          const __half* Ag, size_t lda,
                                          const __half* Bg, size_t ldb, int nchunk) {
    extern __shared__ __half smh[];
    int tid = threadIdx.x;
    int lane = tid & 31, wid = tid >> 5;
    int wrow = wid & 1, wcol = wid >> 1;

    uint32_t a_lofs = (uint32_t)((wrow * 64 + (lane & 15)) * 144 + (lane >> 4) * 16);
    uint32_t b_lofs = (uint32_t)((wcol * 32 + (lane & 15)) * 144 + (lane >> 4) * 16);
    uint32_t sm_base = smem_u32(smh);

#pragma unroll
    for (int mt = 0; mt < 4; mt++)
#pragma unroll
        for (int nt = 0; nt < 4; nt++)
#pragma unroll
            for (int j = 0; j < 4; j++) acc[mt][nt][j] = 0.0f;

    auto load_stage = [&](int c, int s) {
        __half* A_ = smh + s * STAGE_HALVES;
        __half* B_ = A_ + TILE_HALVES;
        load_rm(A_, Ag + (size_t)c * KCH, lda, tid);
        load_rm(B_, Bg + (size_t)c * KCH, ldb, tid);
    };

    load_stage(0, 0); CP_COMMIT();
    load_stage(1, 1); CP_COMMIT();

    for (int c = 0; c < nchunk; c++) {
        CP_WAIT1();
        __syncthreads();
        if (c + 2 < nchunk) load_stage(c + 2, (c + 2) % 3);
        CP_COMMIT();
        uint32_t Aaddr = sm_base + (uint32_t)((c % 3) * STAGE_HALVES) * 2 + a_lofs;
        uint32_t Baddr = sm_base + (uint32_t)((c % 3) * STAGE_HALVES + TILE_HALVES) * 2 + b_lofs;
#pragma unroll
        for (int ks = 0; ks < 4; ks++) {
            uint32_t af[4][4], bf[4][2];
#pragma unroll
            for (int mt = 0; mt < 4; mt++)
                ldsm4(af[mt][0], af[mt][1], af[mt][2], af[mt][3],
                      Aaddr + (uint32_t)(mt * 16 * 144 + ks * 32));
#pragma unroll
            for (int np = 0; np < 2; np++)
                ldsm4(bf[2 * np][0], bf[2 * np + 1][0], bf[2 * np][1], bf[2 * np + 1][1],
                      Baddr + (uint32_t)(np * 16 * 144 + ks * 32));
#pragma unroll
            for (int mt = 0; mt < 4; mt++)
#pragma unroll
                for (int nt = 0; nt < 4; nt++)
                    mma_f16(acc[mt][nt], af[mt], bf[nt]);
        }
    }
}

// ---------------- kernel: prep (transpose x -> fp16; z==2: W->fp16 + zero r,s) ----------------
__global__ void __launch_bounds__(256) k_prep(const float* __restrict__ x,
                                              const float* __restrict__ W) {
    if (blockIdx.z == 2) {
        int id = (blockIdx.y * gridDim.x + blockIdx.x) * 256 + threadIdx.x;
        if (id < OCH * DIM / 4) {
            float4 v = reinterpret_cast<const float4*>(W)[id];
            __half2* dst = reinterpret_cast<__half2*>(g_Wh);
            dst[2 * id]     = __floats2half2_rn(v.x, v.y);
            dst[2 * id + 1] = __floats2half2_rn(v.z, v.w);
        }
        if (id < BATCH * NPIX) { g_r[id] = 0.0f; g_s[id] = 0.0f; }
        return;
    }
    __shared__ float tile[32][33];
    int b  = blockIdx.z;
    int n0 = blockIdx.x * 32;
    int c0 = blockIdx.y * 32;
    int tx = threadIdx.x & 31, ty = threadIdx.x >> 5;
    const float* xb = x + (size_t)b * DIM * NPIX;
#pragma unroll
    for (int i = 0; i < 4; i++) {
        int c = c0 + ty + i * 8;
        tile[ty + i * 8][tx] = xb[(size_t)c * NPIX + n0 + tx];
    }
    __syncthreads();
    __half2* dst = reinterpret_cast<__half2*>(g_xTh + (size_t)b * NPIX * DIM);
    int cpair = threadIdx.x & 15;
    int nrow  = threadIdx.x >> 4;
#pragma unroll
    for (int i = 0; i < 2; i++) {
        int n = n0 + nrow + i * 16;
        dst[((size_t)n * DIM + c0) / 2 + cpair] =
            __floats2half2_rn(tile[cpair * 2][n - n0], tile[cpair * 2 + 1][n - n0]);
    }
}

// ---------------- kernel: qkv 1x1 conv ----------------
__global__ void __launch_bounds__(NTHREADS, 2)
k_qkv(const float* __restrict__ bias) {
    int n0 = blockIdx.x * 128, o0 = blockIdx.y * 128, b = blockIdx.z;
    const __half* Ag = g_xTh + (size_t)(b * NPIX + n0) * DIM;
    const __half* Bg = g_Wh + (size_t)o0 * DIM;

    float acc[4][4][4];
    gemm_main(acc, Ag, DIM, Bg, DIM, DIM / KCH);

    int lane = threadIdx.x & 31, wid = threadIdx.x >> 5;
    int g = lane >> 2, t = lane & 3;
    int wrow = wid & 1, wcol = wid >> 1;
#pragma unroll
    for (int mt = 0; mt < 4; mt++)
#pragma unroll
        for (int half = 0; half < 2; half++) {
            int n = n0 + wrow * 64 + mt * 16 + g + half * 8;
#pragma unroll
            for (int nt = 0; nt < 4; nt++) {
                int o = o0 + wcol * 32 + nt * 8 + 2 * t;
                float v0 = acc[mt][nt][half * 2 + 0] + bias[o];
                float v1 = acc[mt][nt][half * 2 + 1] + bias[o + 1];
                if (o < 256) {
                    *reinterpret_cast<__half2*>(&g_qh[((size_t)(b * NPIX + n)) * DIM + o]) =
                        __floats2half2_rn(v0 * 0.25f, v1 * 0.25f);
                } else if (o < 512) {
                    *reinterpret_cast<__half2*>(&g_kh[((size_t)(b * NPIX + n)) * DIM + (o - 256)]) =
                        __floats2half2_rn(v0 * 0.25f, v1 * 0.25f);
                } else {
                    g_vT[((size_t)b * DIM + (o - 512)) * NPIX + n] = v0;
                    g_vT[((size_t)b * DIM + (o - 511)) * NPIX + n] = v1;
                }
            }
        }
}

// ---------------- kernel: E = exp(Q K^T) + row sums (A-resident, 8 m-tiles per CTA) ----------------
__global__ void __launch_bounds__(NTHREADS, 2)
k_gemmE() {
    extern __shared__ __half smh[];
    uint32_t sm_base = smem_u32(smh);
    int n0 = blockIdx.x * 128;
    int mg = blockIdx.y;                 // 0..3, each covers 1024 m
    int b  = blockIdx.z;
    int tid = threadIdx.x;
    int lane = tid & 31, wid = tid >> 5;
    int wrow = wid & 1, wcol = wid >> 1;

    const __half* Ag = g_qh + (size_t)(b * NPIX + n0) * DIM;
    const __half* Bg = g_kh + (size_t)(b * NPIX + mg * 1024) * DIM;

    // prologue: resident A (4 swizzled chunks), then B chunks g=0,1
#pragma unroll
    for (int kc = 0; kc < 4; kc++)
        load_sw(sm_base + kc * TILE_SW, Ag + kc * KCH, DIM, tid);
    CP_COMMIT();
    load_sw(sm_base + 4 * TILE_SW, Bg, DIM, tid);
    CP_COMMIT();
    load_sw(sm_base + 5 * TILE_SW, Bg + KCH, DIM, tid);
    CP_COMMIT();

    float acc[4][4][4];
    float rs[4][2];
#pragma unroll
    for (int mt = 0; mt < 4; mt++) {
        rs[mt][0] = 0.f; rs[mt][1] = 0.f;
#pragma unroll
        for (int nt = 0; nt < 4; nt++)
#pragma unroll
            for (int j = 0; j < 4; j++) acc[mt][nt][j] = 0.0f;
    }

    int g_ = lane >> 2, t = lane & 3;

    for (int g = 0; g < 32; g++) {
        int kc = g & 3;
        CP_WAIT1();
        __syncthreads();      // all warps done with stage (g+2)%3's previous contents
        if (g + 2 < 32) {
            int h = g + 2;
            load_sw(sm_base + (4 + (h % 3)) * TILE_SW,
                    Bg + (size_t)((h >> 2) * 128) * DIM + (h & 3) * KCH, DIM, tid);
        }
        CP_COMMIT();
        uint32_t Abase = sm_base + (uint32_t)(kc * TILE_SW);
        uint32_t Bbase = sm_base + (uint32_t)((4 + (g % 3)) * TILE_SW);
#pragma unroll
        for (int ks = 0; ks < 4; ks++) {
            uint32_t cc = (uint32_t)(((ks * 2 + (lane >> 4)) ^ (lane & 7)) << 4);
            uint32_t af[4][4], bf[4][2];
#pragma unroll
            for (int mt = 0; mt < 4; mt++) {
                int row = wrow * 64 + mt * 16 + (lane & 15);
                ldsm4(af[mt][0], af[mt][1], af[mt][2], af[mt][3],
                      Abase + (uint32_t)(row * 128) + cc);
            }
#pragma unroll
            for (int np = 0; np < 2; np++) {
                int row = wcol * 32 + np * 16 + (lane & 15);
                ldsm4(bf[2 * np][0], bf[2 * np + 1][0], bf[2 * np][1], bf[2 * np + 1][1],
                      Bbase + (uint32_t)(row * 128) + cc);
            }
#pragma unroll
            for (int mt = 0; mt < 4; mt++)
#pragma unroll
                for (int nt = 0; nt < 4; nt++)
                    mma_f16(acc[mt][nt], af[mt], bf[nt]);
        }
        if (kc == 3) {
            int m0 = (mg * 8 + (g >> 2)) * 128;
#pragma unroll
            for (int mt = 0; mt < 4; mt++)
#pragma unroll
                for (int half = 0; half < 2; half++) {
                    int n = n0 + wrow * 64 + mt * 16 + g_ + half * 8;
                    __half* Erow = g_Eh + ((size_t)b * NPIX + n) * NPIX;
#pragma unroll
                    for (int nt = 0; nt < 4; nt++) {
                        int m = m0 + wcol * 32 + nt * 8 + 2 * t;
                        float e0 = __expf(acc[mt][nt][half * 2 + 0]);
                        float e1 = __expf(acc[mt][nt][half * 2 + 1]);
                        rs[mt][half] += e0 + e1;
                        *reinterpret_cast<__half2*>(&Erow[m]) = __floats2half2_rn(e0, e1);
                        acc[mt][nt][half * 2 + 0] = 0.0f;
                        acc[mt][nt][half * 2 + 1] = 0.0f;
                    }
                }
        }
    }
    // one atomic per row per CTA (4 mgroups contribute per row)
#pragma unroll
    for (int mt = 0; mt < 4; mt++)
#pragma unroll
        for (int half = 0; half < 2; half++) {
            float v = rs[mt][half];
            v += __shfl_xor_sync(0xffffffff, v, 1);
            v += __shfl_xor_sync(0xffffffff, v, 2);
            if (t == 0) {
                int n = n0 + wrow * 64 + mt * 16 + g_ + half * 8;
                atomicAdd(&g_r[b * NPIX + n], v);
            }
        }
}

// ---------------- kernel: split-K partials of sum_m vv[d][m]*E[n][m] ----------------
__global__ void __launch_bounds__(NTHREADS, 2)
k_out(int dummy) {
    int n0 = blockIdx.x * 128;
    int d0 = (blockIdx.y & 1) * 128;
    int split = blockIdx.y >> 1;
    int b = blockIdx.z;
    int kofs = split * (NPIX / NSPLIT);
    const __half* Ag = g_vvTh + ((size_t)b * DIM + d0) * NPIX + kofs;
    const __half* Bg = g_Eh + ((size_t)b * NPIX + n0) * NPIX + kofs;

    float acc[4][4][4];
    gemm_main(acc, Ag, NPIX, Bg, NPIX, NPIX / NSPLIT / KCH);

    int lane = threadIdx.x & 31, wid = threadIdx.x >> 5;
    int g = lane >> 2, t = lane & 3;
    int wrow = wid & 1, wcol = wid >> 1;
    float* P = g_op[split];
#pragma unroll
    for (int mt = 0; mt < 4; mt++)
#pragma unroll
        for (int half = 0; half < 2; half++) {
            int d = d0 + wrow * 64 + mt * 16 + g + half * 8;
            float* prow = P + ((size_t)b * DIM + d) * NPIX;
#pragma unroll
            for (int nt = 0; nt < 4; nt++) {
                int n = n0 + wcol * 32 + nt * 8 + 2 * t;
                *reinterpret_cast<float2*>(&prow[n]) =
                    make_float2(acc[mt][nt][half * 2 + 0], acc[mt][nt][half * 2 + 1]);
            }
        }
}

// ---------------- reduce partials + apply eu ----------------
__global__ void k_red(float* __restrict__ out) {
    int i = blockIdx.x * 256 + threadIdx.x;
    int nb = i & (NPIX / 4 - 1);
    int row = i >> 10;
    int b = row >> 8;
    float4 e = reinterpret_cast<const float4*>(g_eu + b * NPIX)[nb];
    float4 a0 = reinterpret_cast<const float4*>(g_op[0])[i];
    float4 a1 = reinterpret_cast<const float4*>(g_op[1])[i];
    float4 w;
    w.x = (a0.x + a1.x) * e.x;
    w.y = (a0.y + a1.y) * e.y;
    w.z = (a0.z + a1.z) * e.z;
    w.w = (a0.w + a1.w) * e.w;
    reinterpret_cast<float4*>(out)[i] = w;
}

// ---------------- small kernels ----------------
__global__ void k_recip_eu() {
    int i = blockIdx.x * 256 + threadIdx.x;
    if (i < BATCH * NPIX) g_eu[i] = M0 / g_r[i];
}
__global__ void k_recip_ev() {
    int i = blockIdx.x * 256 + threadIdx.x;
    if (i < BATCH * NPIX) g_ev[i] = M0 / g_s[i];
}
__global__ void __launch_bounds__(256) k_colsum() {
    int b = blockIdx.z;
    int m8 = blockIdx.x * 256 + threadIdx.x;
    int n0 = blockIdx.y * 64;
    const float4* Eb = reinterpret_cast<const float4*>(g_Eh + (size_t)b * NPIX * NPIX);
    const float* eub = g_eu + b * NPIX + n0;
    float a[8] = {0, 0, 0, 0, 0, 0, 0, 0};
#pragma unroll 2
    for (int nn = 0; nn < 64; nn++) {
        float4 v = Eb[(size_t)(n0 + nn) * (NPIX / 8) + m8];
        float e = eub[nn];
        const __half2* h = reinterpret_cast<const __half2*>(&v);
#pragma unroll
        for (int j = 0; j < 4; j++) {
            float2 f = __half22float2(h[j]);
            a[2 * j]     += f.x * e;
            a[2 * j + 1] += f.y * e;
        }
    }
    float* s = g_s + b * NPIX + m8 * 8;
#pragma unroll
    for (int j = 0; j < 8; j++) atomicAdd(s + j, a[j]);
}
__global__ void k_scalev() {
    int i = blockIdx.x * 256 + threadIdx.x;
    int m4 = i & (NPIX / 4 - 1);
    int b = i >> 18;
    float4 e = reinterpret_cast<const float4*>(g_ev + b * NPIX)[m4];
    float4 v = reinterpret_cast<const float4*>(g_vT)[i];
    __half2* dst = reinterpret_cast<__half2*>(g_vvTh);
    dst[2 * i]     = __floats2half2_rn(v.x * e.x, v.y * e.y);
    dst[2 * i + 1] = __floats2half2_rn(v.z * e.z, v.w * e.w);
}

// ---------------- launch ----------------
extern "C" void kernel_launch(void* const* d_in, const int* in_sizes, int n_in,
                              void* d_out, int out_size) {
    const float* x    = (const float*)d_in[0];
    const float* W    = (const float*)d_in[1];
    const float* bias = (const float*)d_in[2];
    float* out = (float*)d_out;

    static bool attr_set = false;
    if (!attr_set) {
        cudaFuncSetAttribute(k_qkv,   cudaFuncAttributeMaxDynamicSharedMemorySize, SMEM_BYTES);
        cudaFuncSetAttribute(k_gemmE, cudaFuncAttributeMaxDynamicSharedMemorySize, SMEM_E_BYTES);
        cudaFuncSetAttribute(k_out,   cudaFuncAttributeMaxDynamicSharedMemorySize, SMEM_BYTES);
        attr_set = true;
    }

    k_prep<<<dim3(NPIX / 32, DIM / 32, 3), 256>>>(x, W);
    k_qkv<<<dim3(NPIX / 128, OCH / 128, BATCH), NTHREADS, SMEM_BYTES>>>(bias);
    k_gemmE<<<dim3(NPIX / 128, 4, BATCH), NTHREADS, SMEM_E_BYTES>>>();
    k_recip_eu<<<32, 256>>>();
    k_colsum<<<dim3(NPIX / 8 / 256, NPIX / 64, BATCH), 256>>>();
    k_recip_ev<<<32, 256>>>();
    k_scalev<<<(BATCH * DIM * NPIX / 4) / 256, 256>>>();
    k_out<<<dim3(NPIX / 128, 2 * NSPLIT, BATCH), NTHREADS, SMEM_BYTES>>>(0);
    k_red<<<(BATCH * DIM * NPIX / 4) / 256, 256>>>(out);
}

// round 17
// speedup vs baseline: 1.5541x; 1.5541x over previous
#include <cuda_runtime.h>
#include <cuda_fp16.h>
#include <cstdint>
#include <cstddef>

#define BATCH 2
#define DIM   256
#define NPIX  4096
#define OCH   768
#define KCH   64          // K halves per chunk
#define PITCH_H 72        // smem row pitch in halves (144 B, conflict-free LDSM)
#define NTHREADS 256      // 8 warps, 2x4 grid of 64x32 warp tiles -> CTA 128x128
#define NSPLIT 2
#define TILE_HALVES (128 * PITCH_H)           // 9216 halves = 18432 B per tile
#define STAGE_HALVES (2 * TILE_HALVES)
#define SMEM_BYTES (3 * STAGE_HALVES * 2)     // 110592 B -> 2 CTA/SM

static constexpr float M0 = 1.0f / 4096.0f + 1e-8f;  // exp(logm)

// ---------------- scratch ----------------
__device__ __align__(16) __half g_xTh[BATCH * NPIX * DIM];
__device__ __align__(16) __half g_Wh [OCH * DIM];
__device__ __align__(16) __half g_qh [BATCH * NPIX * DIM];
__device__ __align__(16) __half g_kh [BATCH * NPIX * DIM];
__device__ __align__(16) float  g_vT [BATCH * DIM * NPIX];
__device__ __align__(16) __half g_vvTh[BATCH * DIM * NPIX];
__device__ __align__(16) __half g_Eh [(size_t)BATCH * NPIX * NPIX];
__device__ __align__(16) float g_op [NSPLIT][BATCH * DIM * NPIX];
__device__ __align__(16) float g_r [BATCH * NPIX];
__device__ __align__(16) float g_s [BATCH * NPIX];
__device__ __align__(16) float g_eu[BATCH * NPIX];
__device__ __align__(16) float g_ev[BATCH * NPIX];

// ---------------- helpers ----------------
__device__ __forceinline__ uint32_t smem_u32(const void* p) {
    uint32_t a;
    asm("{ .reg .u64 t; cvta.to.shared.u64 t, %1; cvt.u32.u64 %0, t; }" : "=r"(a) : "l"(p));
    return a;
}
__device__ __forceinline__ void cp16(void* s, const void* g) {
    asm volatile("cp.async.cg.shared.global [%0], [%1], 16;" :: "r"(smem_u32(s)), "l"(g));
}
#define CP_COMMIT() asm volatile("cp.async.commit_group;" ::: "memory")
#define CP_WAIT1()  asm volatile("cp.async.wait_group 1;" ::: "memory")

__device__ __forceinline__ void ldsm4(uint32_t& r0, uint32_t& r1, uint32_t& r2, uint32_t& r3,
                                      uint32_t addr) {
    asm volatile("ldmatrix.sync.aligned.m8n8.x4.shared.b16 {%0,%1,%2,%3}, [%4];"
                 : "=r"(r0), "=r"(r1), "=r"(r2), "=r"(r3) : "r"(addr));
}
__device__ __forceinline__ void mma_f16(float (&d)[4], const uint32_t (&a)[4], const uint32_t (&b)[2]) {
    asm volatile(
        "mma.sync.aligned.m16n8k16.row.col.f32.f16.f16.f32 "
        "{%0,%1,%2,%3}, {%4,%5,%6,%7}, {%8,%9}, {%0,%1,%2,%3};"
        : "+f"(d[0]), "+f"(d[1]), "+f"(d[2]), "+f"(d[3])
        : "r"(a[0]), "r"(a[1]), "r"(a[2]), "r"(a[3]), "r"(b[0]), "r"(b[1]));
}

// 128 rows x 64 halves (128 B) from row-major half src -> smem (pitch 72 halves)
__device__ __forceinline__ void load_rm(__half* sbuf, const __half* src, size_t ld, int tid) {
#pragma unroll
    for (int i = 0; i < 4; i++) {
        int idx = tid + i * NTHREADS;
        int r = idx >> 3;
        int c = (idx & 7) << 3;
        cp16(&sbuf[r * PITCH_H + c], src + (size_t)r * ld + c);
    }
}

// ---------------- 128x128 GEMM mainloop, 8 warps of 64x32, fp16 k16 ----------------
__device__ __forceinline__ void gemm_main(float (&acc)[4][4][4],
                                          const __half* Ag, size_t lda,
                                          const __half* Bg, size_t ldb, int nchunk) {
    extern __shared__ __half smh[];
    int tid = threadIdx.x;
    int lane = tid & 31, wid = tid >> 5;
    int wrow = wid & 1, wcol = wid >> 1;

    uint32_t a_lofs = (uint32_t)((wrow * 64 + (lane & 15)) * 144 + (lane >> 4) * 16);
    uint32_t b_lofs = (uint32_t)((wcol * 32 + (lane & 15)) * 144 + (lane >> 4) * 16);
    uint32_t sm_base = smem_u32(smh);

#pragma unroll
    for (int mt = 0; mt < 4; mt++)
#pragma unroll
        for (int nt = 0; nt < 4; nt++)
#pragma unroll
            for (int j = 0; j < 4; j++) acc[mt][nt][j] = 0.0f;

    auto load_stage = [&](int c, int s) {
        __half* A_ = smh + s * STAGE_HALVES;
        __half* B_ = A_ + TILE_HALVES;
        load_rm(A_, Ag + (size_t)c * KCH, lda, tid);
        load_rm(B_, Bg + (size_t)c * KCH, ldb, tid);
    };

    load_stage(0, 0); CP_COMMIT();
    load_stage(1, 1); CP_COMMIT();

    for (int c = 0; c < nchunk; c++) {
        CP_WAIT1();
        __syncthreads();
        if (c + 2 < nchunk) load_stage(c + 2, (c + 2) % 3);
        CP_COMMIT();
        uint32_t Aaddr = sm_base + (uint32_t)((c % 3) * STAGE_HALVES) * 2 + a_lofs;
        uint32_t Baddr = sm_base + (uint32_t)((c % 3) * STAGE_HALVES + TILE_HALVES) * 2 + b_lofs;
#pragma unroll
        for (int ks = 0; ks < 4; ks++) {
            uint32_t af[4][4], bf[4][2];
#pragma unroll
            for (int mt = 0; mt < 4; mt++)
                ldsm4(af[mt][0], af[mt][1], af[mt][2], af[mt][3],
                      Aaddr + (uint32_t)(mt * 16 * 144 + ks * 32));
#pragma unroll
            for (int np = 0; np < 2; np++)
                ldsm4(bf[2 * np][0], bf[2 * np + 1][0], bf[2 * np][1], bf[2 * np + 1][1],
                      Baddr + (uint32_t)(np * 16 * 144 + ks * 32));
#pragma unroll
            for (int mt = 0; mt < 4; mt++)
#pragma unroll
                for (int nt = 0; nt < 4; nt++)
                    mma_f16(acc[mt][nt], af[mt], bf[nt]);
        }
    }
}

// ---------------- kernel: prep (transpose x -> fp16; z==2: W->fp16 + zero r,s) ----------------
__global__ void __launch_bounds__(256) k_prep(const float* __restrict__ x,
                                              const float* __restrict__ W) {
    if (blockIdx.z == 2) {
        int id = (blockIdx.y * gridDim.x + blockIdx.x) * 256 + threadIdx.x;
        if (id < OCH * DIM / 4) {
            float4 v = reinterpret_cast<const float4*>(W)[id];
            __half2* dst = reinterpret_cast<__half2*>(g_Wh);
            dst[2 * id]     = __floats2half2_rn(v.x, v.y);
            dst[2 * id + 1] = __floats2half2_rn(v.z, v.w);
        }
        if (id < BATCH * NPIX) { g_r[id] = 0.0f; g_s[id] = 0.0f; }
        return;
    }
    __shared__ float tile[32][33];
    int b  = blockIdx.z;
    int n0 = blockIdx.x * 32;
    int c0 = blockIdx.y * 32;
    int tx = threadIdx.x & 31, ty = threadIdx.x >> 5;
    const float* xb = x + (size_t)b * DIM * NPIX;
#pragma unroll
    for (int i = 0; i < 4; i++) {
        int c = c0 + ty + i * 8;
        tile[ty + i * 8][tx] = xb[(size_t)c * NPIX + n0 + tx];
    }
    __syncthreads();
    __half2* dst = reinterpret_cast<__half2*>(g_xTh + (size_t)b * NPIX * DIM);
    int cpair = threadIdx.x & 15;
    int nrow  = threadIdx.x >> 4;
#pragma unroll
    for (int i = 0; i < 2; i++) {
        int n = n0 + nrow + i * 16;
        dst[((size_t)n * DIM + c0) / 2 + cpair] =
            __floats2half2_rn(tile[cpair * 2][n - n0], tile[cpair * 2 + 1][n - n0]);
    }
}

// ---------------- kernel: qkv 1x1 conv ----------------
__global__ void __launch_bounds__(NTHREADS, 2)
k_qkv(const float* __restrict__ bias) {
    int n0 = blockIdx.x * 128, o0 = blockIdx.y * 128, b = blockIdx.z;
    const __half* Ag = g_xTh + (size_t)(b * NPIX + n0) * DIM;
    const __half* Bg = g_Wh + (size_t)o0 * DIM;

    float acc[4][4][4];
    gemm_main(acc, Ag, DIM, Bg, DIM, DIM / KCH);

    int lane = threadIdx.x & 31, wid = threadIdx.x >> 5;
    int g = lane >> 2, t = lane & 3;
    int wrow = wid & 1, wcol = wid >> 1;
#pragma unroll
    for (int mt = 0; mt < 4; mt++)
#pragma unroll
        for (int half = 0; half < 2; half++) {
            int n = n0 + wrow * 64 + mt * 16 + g + half * 8;
#pragma unroll
            for (int nt = 0; nt < 4; nt++) {
                int o = o0 + wcol * 32 + nt * 8 + 2 * t;
                float v0 = acc[mt][nt][half * 2 + 0] + bias[o];
                float v1 = acc[mt][nt][half * 2 + 1] + bias[o + 1];
                if (o < 256) {
                    *reinterpret_cast<__half2*>(&g_qh[((size_t)(b * NPIX + n)) * DIM + o]) =
                        __floats2half2_rn(v0 * 0.25f, v1 * 0.25f);
                } else if (o < 512) {
                    *reinterpret_cast<__half2*>(&g_kh[((size_t)(b * NPIX + n)) * DIM + (o - 256)]) =
                        __floats2half2_rn(v0 * 0.25f, v1 * 0.25f);
                } else {
                    g_vT[((size_t)b * DIM + (o - 512)) * NPIX + n] = v0;
                    g_vT[((size_t)b * DIM + (o - 511)) * NPIX + n] = v1;
                }
            }
        }
}

// ---------------- kernel: E = exp(Q K^T), row sums ----------------
__global__ void __launch_bounds__(NTHREADS, 2)
k_gemmE() {
    int m0 = blockIdx.x * 128, n0 = blockIdx.y * 128, b = blockIdx.z;
    const __half* Ag = g_qh + (size_t)(b * NPIX + n0) * DIM;
    const __half* Bg = g_kh + (size_t)(b * NPIX + m0) * DIM;

    float acc[4][4][4];
    gemm_main(acc, Ag, DIM, Bg, DIM, DIM / KCH);

    int lane = threadIdx.x & 31, wid = threadIdx.x >> 5;
    int g = lane >> 2, t = lane & 3;
    int wrow = wid & 1, wcol = wid >> 1;

#pragma unroll
    for (int mt = 0; mt < 4; mt++)
#pragma unroll
        for (int half = 0; half < 2; half++) {
            int n = n0 + wrow * 64 + mt * 16 + g + half * 8;
            __half* Erow = g_Eh + ((size_t)b * NPIX + n) * NPIX;
            float rs = 0.0f;
#pragma unroll
            for (int nt = 0; nt < 4; nt++) {
                int m = m0 + wcol * 32 + nt * 8 + 2 * t;
                float e0 = __expf(acc[mt][nt][half * 2 + 0]);
                float e1 = __expf(acc[mt][nt][half * 2 + 1]);
                rs += e0 + e1;
                *reinterpret_cast<__half2*>(&Erow[m]) = __floats2half2_rn(e0, e1);
            }
            float v = rs;
            v += __shfl_xor_sync(0xffffffff, v, 1);
            v += __shfl_xor_sync(0xffffffff, v, 2);
            if (t == 0) atomicAdd(&g_r[b * NPIX + n], v);
        }
}

// ---------------- kernel: split-K partials of sum_m vv[d][m]*E[n][m] ----------------
__global__ void __launch_bounds__(NTHREADS, 2)
k_out(int dummy) {
    int n0 = blockIdx.x * 128;
    int d0 = (blockIdx.y & 1) * 128;
    int split = blockIdx.y >> 1;
    int b = blockIdx.z;
    int kofs = split * (NPIX / NSPLIT);
    const __half* Ag = g_vvTh + ((size_t)b * DIM + d0) * NPIX + kofs;
    const __half* Bg = g_Eh + ((size_t)b * NPIX + n0) * NPIX + kofs;

    float acc[4][4][4];
    gemm_main(acc, Ag, NPIX, Bg, NPIX, NPIX / NSPLIT / KCH);

    int lane = threadIdx.x & 31, wid = threadIdx.x >> 5;
    int g = lane >> 2, t = lane & 3;
    int wrow = wid & 1, wcol = wid >> 1;
    float* P = g_op[split];
#pragma unroll
    for (int mt = 0; mt < 4; mt++)
#pragma unroll
        for (int half = 0; half < 2; half++) {
            int d = d0 + wrow * 64 + mt * 16 + g + half * 8;
            float* prow = P + ((size_t)b * DIM + d) * NPIX;
#pragma unroll
            for (int nt = 0; nt < 4; nt++) {
                int n = n0 + wcol * 32 + nt * 8 + 2 * t;
                *reinterpret_cast<float2*>(&prow[n]) =
                    make_float2(acc[mt][nt][half * 2 + 0], acc[mt][nt][half * 2 + 1]);
            }
        }
}

// ---------------- reduce partials + apply eu ----------------
__global__ void k_red(float* __restrict__ out) {
    int i = blockIdx.x * 256 + threadIdx.x;
    int nb = i & (NPIX / 4 - 1);
    int row = i >> 10;
    int b = row >> 8;
    float4 e = reinterpret_cast<const float4*>(g_eu + b * NPIX)[nb];
    float4 a0 = reinterpret_cast<const float4*>(g_op[0])[i];
    float4 a1 = reinterpret_cast<const float4*>(g_op[1])[i];
    float4 w;
    w.x = (a0.x + a1.x) * e.x;
    w.y = (a0.y + a1.y) * e.y;
    w.z = (a0.z + a1.z) * e.z;
    w.w = (a0.w + a1.w) * e.w;
    reinterpret_cast<float4*>(out)[i] = w;
}

// ---------------- small kernels ----------------
__global__ void k_recip_ev() {
    int i = blockIdx.x * 256 + threadIdx.x;
    if (i < BATCH * NPIX) g_ev[i] = M0 / g_s[i];
}
// s[m] = sum_n E[n][m]*eu[n], with eu computed in-kernel from g_r (also persisted to g_eu)
__global__ void __launch_bounds__(256) k_colsum() {
    __shared__ float seu[64];
    int b = blockIdx.z;
    int m8 = blockIdx.x * 256 + threadIdx.x;
    int n0 = blockIdx.y * 64;
    if (threadIdx.x < 64) {
        float e = M0 / g_r[b * NPIX + n0 + threadIdx.x];
        seu[threadIdx.x] = e;
        if (blockIdx.x == 0) g_eu[b * NPIX + n0 + threadIdx.x] = e;
    }
    __syncthreads();
    const float4* Eb = reinterpret_cast<const float4*>(g_Eh + (size_t)b * NPIX * NPIX);
    float a[8] = {0, 0, 0, 0, 0, 0, 0, 0};
#pragma unroll 2
    for (int nn = 0; nn < 64; nn++) {
        float4 v = Eb[(size_t)(n0 + nn) * (NPIX / 8) + m8];
        float e = seu[nn];
        const __half2* h = reinterpret_cast<const __half2*>(&v);
#pragma unroll
        for (int j = 0; j < 4; j++) {
            float2 f = __half22float2(h[j]);
            a[2 * j]     += f.x * e;
            a[2 * j + 1] += f.y * e;
        }
    }
    float* s = g_s + b * NPIX + m8 * 8;
#pragma unroll
    for (int j = 0; j < 8; j++) atomicAdd(s + j, a[j]);
}
__global__ void k_scalev() {
    int i = blockIdx.x * 256 + threadIdx.x;
    int m4 = i & (NPIX / 4 - 1);
    int b = i >> 18;
    float4 e = reinterpret_cast<const float4*>(g_ev + b * NPIX)[m4];
    float4 v = reinterpret_cast<const float4*>(g_vT)[i];
    __half2* dst = reinterpret_cast<__half2*>(g_vvTh);
    dst[2 * i]     = __floats2half2_rn(v.x * e.x, v.y * e.y);
    dst[2 * i + 1] = __floats2half2_rn(v.z * e.z, v.w * e.w);
}

// ---------------- launch ----------------
extern "C" void kernel_launch(void* const* d_in, const int* in_sizes, int n_in,
                              void* d_out, int out_size) {
    const float* x    = (const float*)d_in[0];
    const float* W    = (const float*)d_in[1];
    const float* bias = (const float*)d_in[2];
    float* out = (float*)d_out;

    static bool attr_set = false;
    if (!attr_set) {
        cudaFuncSetAttribute(k_qkv,   cudaFuncAttributeMaxDynamicSharedMemorySize, SMEM_BYTES);
        cudaFuncSetAttribute(k_gemmE, cudaFuncAttributeMaxDynamicSharedMemorySize, SMEM_BYTES);
        cudaFuncSetAttribute(k_out,   cudaFuncAttributeMaxDynamicSharedMemorySize, SMEM_BYTES);
        attr_set = true;
    }

    k_prep<<<dim3(NPIX / 32, DIM / 32, 3), 256>>>(x, W);
    k_qkv<<<dim3(NPIX / 128, OCH / 128, BATCH), NTHREADS, SMEM_BYTES>>>(bias);
    k_gemmE<<<dim3(NPIX / 128, NPIX / 128, BATCH), NTHREADS, SMEM_BYTES>>>();
    k_colsum<<<dim3(NPIX / 8 / 256, NPIX / 64, BATCH), 256>>>();
    k_recip_ev<<<32, 256>>>();
    k_scalev<<<(BATCH * DIM * NPIX / 4) / 256, 256>>>();
    k_out<<<dim3(NPIX / 128, 2 * NSPLIT, BATCH), NTHREADS, SMEM_BYTES>>>(0);
    k_red<<<(BATCH * DIM * NPIX / 4) / 256, 256>>>(out);
}